// round 1
// baseline (speedup 1.0000x reference)
#include <cuda_runtime.h>

#define NN 96
#define NP 9216            // 96*96
#define NVOX 884736        // 96^3
#define NFIELDS 8
#define NPAIRS 6
#define VSTEPS 7
#define TPB 256
#define NBLK (NVOX / TPB)  // 3456

// Ping-pong scratch: field f layout (vx,vy,vz,0) per voxel, voxel-major (x outer, z inner)
__device__ float4 g_A[NFIELDS][NVOX];
__device__ float4 g_B[NFIELDS][NVOX];
__device__ double g_part[NPAIRS * NBLK];

__device__ __forceinline__ float lp(float a, float b, float t) {
    return fmaf(t, b - a, a);
}

// Trilinear sample of a (vx,vy,vz) float4 field at absolute coords, reference clamp semantics
__device__ __forceinline__ float4 trisample(const float4* __restrict__ vol,
                                            float cx, float cy, float cz) {
    float xf = floorf(cx), yf = floorf(cy), zf = floorf(cz);
    float fx = cx - xf, fy = cy - yf, fz = cz - zf;
    int x0 = min(max((int)xf, 0), NN - 1); int x1 = min(x0 + 1, NN - 1);
    int y0 = min(max((int)yf, 0), NN - 1); int y1 = min(y0 + 1, NN - 1);
    int z0 = min(max((int)zf, 0), NN - 1); int z1 = min(z0 + 1, NN - 1);

    const float4* r00 = vol + x0 * NP + y0 * NN;
    const float4* r01 = vol + x0 * NP + y1 * NN;
    const float4* r10 = vol + x1 * NP + y0 * NN;
    const float4* r11 = vol + x1 * NP + y1 * NN;

    float4 c000 = r00[z0], c001 = r00[z1];
    float4 c010 = r01[z0], c011 = r01[z1];
    float4 c100 = r10[z0], c101 = r10[z1];
    float4 c110 = r11[z0], c111 = r11[z1];

    float4 out;
    {
        float c00 = lp(c000.x, c001.x, fz), c01 = lp(c010.x, c011.x, fz);
        float c10 = lp(c100.x, c101.x, fz), c11 = lp(c110.x, c111.x, fz);
        out.x = lp(lp(c00, c01, fy), lp(c10, c11, fy), fx);
    }
    {
        float c00 = lp(c000.y, c001.y, fz), c01 = lp(c010.y, c011.y, fz);
        float c10 = lp(c100.y, c101.y, fz), c11 = lp(c110.y, c111.y, fz);
        out.y = lp(lp(c00, c01, fy), lp(c10, c11, fy), fx);
    }
    {
        float c00 = lp(c000.z, c001.z, fz), c01 = lp(c010.z, c011.z, fz);
        float c10 = lp(c100.z, c101.z, fz), c11 = lp(c110.z, c111.z, fz);
        out.z = lp(lp(c00, c01, fy), lp(c10, c11, fy), fx);
    }
    out.w = 0.f;
    return out;
}

// v0 = sign * T[tp] / 2^7 for 8 fields (even f = +, odd f = -)
__global__ void __launch_bounds__(TPB) k_init(const float* __restrict__ T) {
    int idx = blockIdx.x * TPB + threadIdx.x;
    int f = blockIdx.y;
    int tp = f >> 1;
    float s = (f & 1) ? -0.0078125f : 0.0078125f;
    const float* base = T + (size_t)tp * 3 * NVOX;
    float4 v;
    v.x = s * base[idx];
    v.y = s * base[idx + NVOX];
    v.z = s * base[idx + 2 * NVOX];
    v.w = 0.f;
    g_A[f][idx] = v;
}

// One scaling-and-squaring step for all 8 fields: out = v + sample(v, grid+v)
__global__ void __launch_bounds__(TPB) k_step(int dir) {
    const float4* __restrict__ inb = dir ? &g_B[0][0] : &g_A[0][0];
    float4* __restrict__ outb = dir ? &g_A[0][0] : &g_B[0][0];
    int idx = blockIdx.x * TPB + threadIdx.x;
    int f = blockIdx.y;
    const float4* vol = inb + f * NVOX;

    float4 v = vol[idx];
    int z = idx % NN;
    int t = idx / NN;
    int y = t % NN;
    int x = t / NN;

    float4 s = trisample(vol, (float)x + v.x, (float)y + v.y, (float)z + v.z);
    float4 o;
    o.x = v.x + s.x; o.y = v.y + s.y; o.z = v.z + s.z; o.w = 0.f;
    outb[f * NVOX + idx] = o;
}

__constant__ int c_ref[NPAIRS] = {0, 0, 0, 1, 1, 2};
__constant__ int c_flo[NPAIRS] = {1, 2, 3, 2, 3, 3};

// Compose + residual norm, block partial sums (results of 7 steps live in g_B)
__global__ void __launch_bounds__(TPB) k_final(const float* __restrict__ R) {
    __shared__ double sred[TPB / 32];
    int idx = blockIdx.x * TPB + threadIdx.x;
    int p = blockIdx.y;
    const float4* fneg = &g_B[2 * c_ref[p] + 1][0];
    const float4* fpos = &g_B[2 * c_flo[p]][0];

    float4 v = fneg[idx];
    int z = idx % NN;
    int t = idx / NN;
    int y = t % NN;
    int x = t / NN;

    float4 s = trisample(fpos, (float)x + v.x, (float)y + v.y, (float)z + v.z);
    // R layout: (x,y,z,c,p) -> idx*18 + c*6 + p
    float rx = v.x + s.x - R[idx * 18 + 0 + p];
    float ry = v.y + s.y - R[idx * 18 + 6 + p];
    float rz = v.z + s.z - R[idx * 18 + 12 + p];
    float term = sqrtf(rx * rx + ry * ry + rz * rz);

    #pragma unroll
    for (int o = 16; o; o >>= 1) term += __shfl_down_sync(0xffffffffu, term, o);

    int lane = threadIdx.x & 31, w = threadIdx.x >> 5;
    if (lane == 0) sred[w] = (double)term;
    __syncthreads();
    if (threadIdx.x == 0) {
        double acc = 0.0;
        #pragma unroll
        for (int i = 0; i < TPB / 32; i++) acc += sred[i];
        g_part[p * NBLK + blockIdx.x] = acc;
    }
}

// Deterministic final reduction of block partials
__global__ void __launch_bounds__(1024) k_reduce(float* __restrict__ out) {
    __shared__ double sred[32];
    double acc = 0.0;
    const int n = NPAIRS * NBLK;
    for (int i = threadIdx.x; i < n; i += 1024) acc += g_part[i];
    #pragma unroll
    for (int o = 16; o; o >>= 1) acc += __shfl_down_sync(0xffffffffu, acc, o);
    int lane = threadIdx.x & 31, w = threadIdx.x >> 5;
    if (lane == 0) sred[w] = acc;
    __syncthreads();
    if (threadIdx.x == 0) {
        double tot = 0.0;
        #pragma unroll
        for (int i = 0; i < 32; i++) tot += sred[i];
        out[0] = (float)tot;
    }
}

extern "C" void kernel_launch(void* const* d_in, const int* in_sizes, int n_in,
                              void* d_out, int out_size) {
    const float* T = (const float*)d_in[0];
    const float* R = (const float*)d_in[1];
    // Robust to metadata ordering: T has 4*3*96^3 = 10,616,832 elems; R has 96^3*18 = 15,925,248
    if (n_in >= 2 && in_sizes[0] == 15925248) {
        T = (const float*)d_in[1];
        R = (const float*)d_in[0];
    }
    float* out = (float*)d_out;

    dim3 blk(TPB);
    dim3 gi(NBLK, NFIELDS);
    k_init<<<gi, blk>>>(T);
    for (int s = 0; s < VSTEPS; s++) {
        k_step<<<gi, blk>>>(s & 1);  // step 0 reads g_A writes g_B; alternates; ends in g_B
    }
    dim3 gf(NBLK, NPAIRS);
    k_final<<<gf, blk>>>(R);
    k_reduce<<<1, 1024>>>(out);
}

// round 2
// speedup vs baseline: 1.5545x; 1.5545x over previous
#include <cuda_runtime.h>
#include <cuda_fp16.h>

#define NN 96
#define NP 9216            // 96*96
#define NVOX 884736        // 96^3
#define NFIELDS 8
#define NPAIRS 6
#define VSTEPS 7
#define TPB 256
#define NBLK (NVOX / TPB)  // 3456

// Ping-pong scratch: field stored as packed half4 (vx,vy,vz,pad) = 8 bytes/voxel
__device__ uint2 g_A[NFIELDS][NVOX];
__device__ uint2 g_B[NFIELDS][NVOX];
__device__ float g_Rt[NPAIRS][3][NVOX];   // transposed R: (pair, channel, voxel)
__device__ double g_part[NPAIRS * NBLK];

__device__ __forceinline__ float lp(float a, float b, float t) {
    return fmaf(t, b - a, a);
}

__device__ __forceinline__ float3 unpackv(uint2 u) {
    __half2 h0 = *reinterpret_cast<__half2*>(&u.x);
    __half2 h1 = *reinterpret_cast<__half2*>(&u.y);
    float2 a = __half22float2(h0);
    float2 b = __half22float2(h1);
    return make_float3(a.x, a.y, b.x);
}

__device__ __forceinline__ uint2 packv(float x, float y, float z) {
    __half2 h0 = __floats2half2_rn(x, y);
    __half2 h1 = __floats2half2_rn(z, 0.f);
    uint2 u;
    u.x = *reinterpret_cast<unsigned*>(&h0);
    u.y = *reinterpret_cast<unsigned*>(&h1);
    return u;
}

// Trilinear sample of packed-half field at absolute coords, reference clamp semantics:
// x0 = clip(floor, 0, N-1), x1 = clip(x0+1, 0, N-1), fractional part NOT clamped.
__device__ __forceinline__ float3 trisample(const uint2* __restrict__ vol,
                                            float cx, float cy, float cz) {
    float xf = floorf(cx), yf = floorf(cy), zf = floorf(cz);
    float fx = cx - xf, fy = cy - yf, fz = cz - zf;
    int x0 = min(max((int)xf, 0), NN - 1); int x1 = min(x0 + 1, NN - 1);
    int y0 = min(max((int)yf, 0), NN - 1); int y1 = min(y0 + 1, NN - 1);
    int z0 = min(max((int)zf, 0), NN - 1); int z1 = min(z0 + 1, NN - 1);

    const uint2* r00 = vol + x0 * NP + y0 * NN;
    const uint2* r01 = vol + x0 * NP + y1 * NN;
    const uint2* r10 = vol + x1 * NP + y0 * NN;
    const uint2* r11 = vol + x1 * NP + y1 * NN;

    float3 c000 = unpackv(__ldg(r00 + z0)), c001 = unpackv(__ldg(r00 + z1));
    float3 c010 = unpackv(__ldg(r01 + z0)), c011 = unpackv(__ldg(r01 + z1));
    float3 c100 = unpackv(__ldg(r10 + z0)), c101 = unpackv(__ldg(r10 + z1));
    float3 c110 = unpackv(__ldg(r11 + z0)), c111 = unpackv(__ldg(r11 + z1));

    float3 out;
    {
        float c00 = lp(c000.x, c001.x, fz), c01 = lp(c010.x, c011.x, fz);
        float c10 = lp(c100.x, c101.x, fz), c11 = lp(c110.x, c111.x, fz);
        out.x = lp(lp(c00, c01, fy), lp(c10, c11, fy), fx);
    }
    {
        float c00 = lp(c000.y, c001.y, fz), c01 = lp(c010.y, c011.y, fz);
        float c10 = lp(c100.y, c101.y, fz), c11 = lp(c110.y, c111.y, fz);
        out.y = lp(lp(c00, c01, fy), lp(c10, c11, fy), fx);
    }
    {
        float c00 = lp(c000.z, c001.z, fz), c01 = lp(c010.z, c011.z, fz);
        float c10 = lp(c100.z, c101.z, fz), c11 = lp(c110.z, c111.z, fz);
        out.z = lp(lp(c00, c01, fy), lp(c10, c11, fy), fx);
    }
    return out;
}

// v0 = sign * T[tp] / 2^7 for 8 fields (even f = +, odd f = -)
__global__ void __launch_bounds__(TPB) k_init(const float* __restrict__ T) {
    int idx = blockIdx.x * TPB + threadIdx.x;
    int f = blockIdx.y;
    int tp = f >> 1;
    float s = (f & 1) ? -0.0078125f : 0.0078125f;
    const float* base = T + (size_t)tp * 3 * NVOX;
    g_A[f][idx] = packv(s * base[idx], s * base[idx + NVOX], s * base[idx + 2 * NVOX]);
}

// Transpose R (x,y,z,c,p) -> (p,c,voxel) with smem staging for coalesced I/O
__global__ void __launch_bounds__(TPB) k_transpose(const float* __restrict__ R) {
    __shared__ float s[TPB * 18];
    int base = blockIdx.x * TPB;
    for (int j = threadIdx.x; j < TPB * 18; j += TPB)
        s[j] = R[(size_t)base * 18 + j];
    __syncthreads();
    int idx = base + threadIdx.x;
    #pragma unroll
    for (int c = 0; c < 3; c++)
        #pragma unroll
        for (int p = 0; p < NPAIRS; p++)
            g_Rt[p][c][idx] = s[threadIdx.x * 18 + c * 6 + p];
}

// One scaling-and-squaring step for all 8 fields: out = v + sample(v, grid+v)
__global__ void __launch_bounds__(TPB) k_step(int dir) {
    const uint2* __restrict__ inb = dir ? &g_B[0][0] : &g_A[0][0];
    uint2* __restrict__ outb = dir ? &g_A[0][0] : &g_B[0][0];
    int idx = blockIdx.x * TPB + threadIdx.x;
    int f = blockIdx.y;
    const uint2* vol = inb + f * NVOX;

    float3 v = unpackv(vol[idx]);
    int z = idx % NN;
    int t = idx / NN;
    int y = t % NN;
    int x = t / NN;

    float3 s = trisample(vol, (float)x + v.x, (float)y + v.y, (float)z + v.z);
    outb[f * NVOX + idx] = packv(v.x + s.x, v.y + s.y, v.z + s.z);
}

__constant__ int c_ref[NPAIRS] = {0, 0, 0, 1, 1, 2};
__constant__ int c_flo[NPAIRS] = {1, 2, 3, 2, 3, 3};

// Compose + residual norm, block partial sums (results of 7 steps live in g_B)
__global__ void __launch_bounds__(TPB) k_final() {
    __shared__ double sred[TPB / 32];
    int idx = blockIdx.x * TPB + threadIdx.x;
    int p = blockIdx.y;
    const uint2* fneg = &g_B[2 * c_ref[p] + 1][0];
    const uint2* fpos = &g_B[2 * c_flo[p]][0];

    float3 v = unpackv(fneg[idx]);
    int z = idx % NN;
    int t = idx / NN;
    int y = t % NN;
    int x = t / NN;

    float3 s = trisample(fpos, (float)x + v.x, (float)y + v.y, (float)z + v.z);
    float rx = v.x + s.x - g_Rt[p][0][idx];
    float ry = v.y + s.y - g_Rt[p][1][idx];
    float rz = v.z + s.z - g_Rt[p][2][idx];
    float term = sqrtf(rx * rx + ry * ry + rz * rz);

    #pragma unroll
    for (int o = 16; o; o >>= 1) term += __shfl_down_sync(0xffffffffu, term, o);

    int lane = threadIdx.x & 31, w = threadIdx.x >> 5;
    if (lane == 0) sred[w] = (double)term;
    __syncthreads();
    if (threadIdx.x == 0) {
        double acc = 0.0;
        #pragma unroll
        for (int i = 0; i < TPB / 32; i++) acc += sred[i];
        g_part[p * NBLK + blockIdx.x] = acc;
    }
}

// Deterministic final reduction of block partials
__global__ void __launch_bounds__(1024) k_reduce(float* __restrict__ out) {
    __shared__ double sred[32];
    double acc = 0.0;
    const int n = NPAIRS * NBLK;
    for (int i = threadIdx.x; i < n; i += 1024) acc += g_part[i];
    #pragma unroll
    for (int o = 16; o; o >>= 1) acc += __shfl_down_sync(0xffffffffu, acc, o);
    int lane = threadIdx.x & 31, w = threadIdx.x >> 5;
    if (lane == 0) sred[w] = acc;
    __syncthreads();
    if (threadIdx.x == 0) {
        double tot = 0.0;
        #pragma unroll
        for (int i = 0; i < 32; i++) tot += sred[i];
        out[0] = (float)tot;
    }
}

extern "C" void kernel_launch(void* const* d_in, const int* in_sizes, int n_in,
                              void* d_out, int out_size) {
    const float* T = (const float*)d_in[0];
    const float* R = (const float*)d_in[1];
    // Robust to metadata ordering: T has 4*3*96^3 = 10,616,832 elems; R has 96^3*18 = 15,925,248
    if (n_in >= 2 && in_sizes[0] == 15925248) {
        T = (const float*)d_in[1];
        R = (const float*)d_in[0];
    }
    float* out = (float*)d_out;

    dim3 blk(TPB);
    dim3 gi(NBLK, NFIELDS);
    k_init<<<gi, blk>>>(T);
    k_transpose<<<NBLK, TPB>>>(R);
    for (int s = 0; s < VSTEPS; s++) {
        k_step<<<gi, blk>>>(s & 1);  // step 0 reads g_A writes g_B; alternates; ends in g_B
    }
    dim3 gf(NBLK, NPAIRS);
    k_final<<<gf, blk>>>();
    k_reduce<<<1, 1024>>>(out);
}